// round 2
// baseline (speedup 1.0000x reference)
#include <cuda_runtime.h>
#include <math.h>

// Problem constants
#define B_  64
#define T_  32
#define S_  33
#define V_  32000
#define E_  512
#define H_  1024
#define G4  4096
#define M1  (S_*B_)       // 2112

// GEMM config: CTA tile 64x256, 128 threads, thread tile 8m x 16n (n-packed f32x2)
#define KSPLIT 8
#define BM 64
#define BN 256
#define BK 16
#define NT 128
#define NTILES (G4/BN)    // 16

// Scratch
__device__ float g_x   [M1 * E_];
__device__ float g_xg  [M1 * G4];
__device__ float g_h   [B_ * H_];
__device__ float g_c   [B_ * H_];
__device__ float g_part[KSPLIT * B_ * G4];
__device__ unsigned g_cnt[NTILES];   // zero-init; each winner resets its slot

typedef unsigned long long u64;

__device__ __forceinline__ void ffma2(u64& d, u64 a, u64 b) {
    asm("fma.rn.f32x2 %0, %1, %2, %0;" : "+l"(d) : "l"(a), "l"(b));
}
__device__ __forceinline__ u64 splat2(float x) {
    u64 r; asm("mov.b64 %0, {%1, %1};" : "=l"(r) : "f"(x)); return r;
}
__device__ __forceinline__ float sigf(float x) {
    return 1.0f / (1.0f + __expf(-x));
}
__device__ __forceinline__ float tanhfast(float x) {
    return 2.0f / (1.0f + __expf(-2.0f * x)) - 1.0f;
}

// ---------------------------------------------------------------------------
// 1) Gather inputs: row m = t*64+b ; t==0 -> features, else W_embed column
// ---------------------------------------------------------------------------
__global__ void build_x_kernel(const float* __restrict__ features,
                               const int*   __restrict__ captions,
                               const float* __restrict__ W_embed,
                               const float* __restrict__ b_embed) {
    int idx = blockIdx.x * blockDim.x + threadIdx.x;
    if (idx >= M1 * E_) return;
    int m = idx >> 9;
    int e = idx & 511;
    int t = m >> 6;
    int b = m & 63;
    float v;
    if (t == 0) {
        v = features[b * E_ + e];
    } else {
        int cap = captions[b * T_ + (t - 1)];
        v = W_embed[e * V_ + cap] + b_embed[e];
    }
    g_x[idx] = v;
}

// ---------------------------------------------------------------------------
// 2) NT GEMM 64x256 tile, 8mx16n threads, double-buffered smem, f32x2 FMA.
//    STEP=true: B columns gate-interleaved (n-tile owns full i,f,g,o quads),
//    split-K partials + atomic-counter fused LSTM epilogue by the last CTA.
//    STEP=false: plain C write (input projection xg).
// ---------------------------------------------------------------------------
template<bool STEP>
__global__ __launch_bounds__(NT)
void gemm_kernel(const float* __restrict__ A,     // [M, K]
                 const float* __restrict__ Bw,    // [4096, K]
                 int K, int kLen,
                 float* C,                        // xg or partials (no restrict!)
                 int t,
                 const float* __restrict__ xg,
                 const float* __restrict__ b_ih,
                 const float* __restrict__ b_hh,
                 float* __restrict__ out) {
    __shared__ float As[2][BK][BM];
    __shared__ float Bs[2][BK][BN];

    const int tid = threadIdx.x;
    const int nt  = blockIdx.x;
    const int m0  = blockIdx.y * BM;
    const int z   = blockIdx.z;
    const int kStart = z * kLen;

    // global-load lanes: 32 row-slots x 4 k-quads
    const int lr = tid >> 2;
    const int lq = tid & 3;

    const float* Ap0 = A + (size_t)(m0 + lr) * K + kStart + lq * 4;
    const float* Ap1 = Ap0 + (size_t)32 * K;

    const float* Bp[8];
#pragma unroll
    for (int i = 0; i < 8; i++) {
        int n = lr + 32 * i;
        int grow;
        if (STEP) grow = (n >> 6) * H_ + nt * 64 + (n & 63);  // gate-interleaved
        else      grow = nt * BN + n;                          // plain
        Bp[i] = Bw + (size_t)grow * K + kStart + lq * 4;
    }

    u64 acc[8][8];
#pragma unroll
    for (int i = 0; i < 8; i++)
#pragma unroll
        for (int j = 0; j < 8; j++) acc[i][j] = 0ull;

    const int mg = tid >> 4;   // 0..7
    const int ng = tid & 15;   // 0..15
    const int nk = kLen / BK;

    // initial prefetch
    float4 pa0 = *(const float4*)Ap0;
    float4 pa1 = *(const float4*)Ap1;
    float4 pb[8];
#pragma unroll
    for (int i = 0; i < 8; i++) pb[i] = *(const float4*)(Bp[i]);

    for (int kt = 0; kt < nk; kt++) {
        const int cur = kt & 1;
        // commit prefetched regs to smem (transposed [k][mn])
        As[cur][lq*4+0][lr]    = pa0.x; As[cur][lq*4+1][lr]    = pa0.y;
        As[cur][lq*4+2][lr]    = pa0.z; As[cur][lq*4+3][lr]    = pa0.w;
        As[cur][lq*4+0][lr+32] = pa1.x; As[cur][lq*4+1][lr+32] = pa1.y;
        As[cur][lq*4+2][lr+32] = pa1.z; As[cur][lq*4+3][lr+32] = pa1.w;
#pragma unroll
        for (int i = 0; i < 8; i++) {
            Bs[cur][lq*4+0][lr+32*i] = pb[i].x;
            Bs[cur][lq*4+1][lr+32*i] = pb[i].y;
            Bs[cur][lq*4+2][lr+32*i] = pb[i].z;
            Bs[cur][lq*4+3][lr+32*i] = pb[i].w;
        }
        __syncthreads();

        // prefetch next tile (overlaps with compute below)
        if (kt + 1 < nk) {
            int off = (kt + 1) * BK;
            pa0 = *(const float4*)(Ap0 + off);
            pa1 = *(const float4*)(Ap1 + off);
#pragma unroll
            for (int i = 0; i < 8; i++) pb[i] = *(const float4*)(Bp[i] + off);
        }

#pragma unroll
        for (int kk = 0; kk < BK; kk++) {
            float4 f0 = *(const float4*)&As[cur][kk][mg * 8];
            float4 f1 = *(const float4*)&As[cur][kk][mg * 8 + 4];
            u64 sa0 = splat2(f0.x), sa1 = splat2(f0.y);
            u64 sa2 = splat2(f0.z), sa3 = splat2(f0.w);
            u64 sa4 = splat2(f1.x), sa5 = splat2(f1.y);
            u64 sa6 = splat2(f1.z), sa7 = splat2(f1.w);
            u64 b2[8];
#pragma unroll
            for (int jj = 0; jj < 8; jj++)
                b2[jj] = *(const u64*)&Bs[cur][kk][2 * ng + 32 * jj];
#pragma unroll
            for (int jj = 0; jj < 8; jj++) {
                ffma2(acc[0][jj], sa0, b2[jj]);
                ffma2(acc[1][jj], sa1, b2[jj]);
                ffma2(acc[2][jj], sa2, b2[jj]);
                ffma2(acc[3][jj], sa3, b2[jj]);
                ffma2(acc[4][jj], sa4, b2[jj]);
                ffma2(acc[5][jj], sa5, b2[jj]);
                ffma2(acc[6][jj], sa6, b2[jj]);
                ffma2(acc[7][jj], sa7, b2[jj]);
            }
        }
    }

    // write C (xg for big; k-split partial for step)
#pragma unroll
    for (int i = 0; i < 8; i++) {
        int m = m0 + mg * 8 + i;
        float* crow;
        if (STEP) crow = C + (size_t)z * (B_ * G4) + (size_t)m * G4 + nt * BN;
        else      crow = C + (size_t)m * G4 + nt * BN;
#pragma unroll
        for (int jj = 0; jj < 8; jj++) {
            *(float2*)&crow[2 * ng + 32 * jj] = *(float2*)&acc[i][jj];
        }
    }

    if (STEP) {
        __threadfence();                 // release partial stores
        __shared__ unsigned s_last;
        __syncthreads();                 // all threads stored+fenced
        if (tid == 0) {
            unsigned old = atomicAdd(&g_cnt[nt], 1u);
            s_last = (old == KSPLIT - 1) ? 1u : 0u;
        }
        __syncthreads();
        if (!s_last) return;
        if (tid == 0) g_cnt[nt] = 0;     // reset for next launch / graph replay
        __threadfence();                 // acquire partials from all slices

        // fused LSTM cell update for this n-tile's 64 cell columns x 64 rows
#pragma unroll
        for (int r = 0; r < 8; r++) {
            int id = r * NT + tid;       // 0..1023
            int m  = id >> 4;            // batch row
            int c4 = (id & 15) * 4;      // cell-col group of 4
            float4 gv[4];
#pragma unroll
            for (int g = 0; g < 4; g++) {
                int ncol = g * H_ + nt * 64 + c4;
                float4 s  = *(const float4*)&xg[(size_t)(t * B_ + m) * G4 + ncol];
                float4 bi = *(const float4*)&b_ih[ncol];
                float4 bh = *(const float4*)&b_hh[ncol];
                s.x += bi.x + bh.x; s.y += bi.y + bh.y;
                s.z += bi.z + bh.z; s.w += bi.w + bh.w;
#pragma unroll
                for (int zz = 0; zz < KSPLIT; zz++) {
                    const float4 p = *(const float4*)
                        &g_part[(size_t)zz * (B_ * G4) + (size_t)m * G4 + nt * BN + g * 64 + c4];
                    s.x += p.x; s.y += p.y; s.z += p.z; s.w += p.w;
                }
                gv[g] = s;
            }
            int hidx = m * H_ + nt * 64 + c4;
            float4 cold = *(const float4*)&g_c[hidx];
            float4 cnew, hnew;
            cnew.x = sigf(gv[1].x) * cold.x + sigf(gv[0].x) * tanhfast(gv[2].x);
            cnew.y = sigf(gv[1].y) * cold.y + sigf(gv[0].y) * tanhfast(gv[2].y);
            cnew.z = sigf(gv[1].z) * cold.z + sigf(gv[0].z) * tanhfast(gv[2].z);
            cnew.w = sigf(gv[1].w) * cold.w + sigf(gv[0].w) * tanhfast(gv[2].w);
            hnew.x = sigf(gv[3].x) * tanhfast(cnew.x);
            hnew.y = sigf(gv[3].y) * tanhfast(cnew.y);
            hnew.z = sigf(gv[3].z) * tanhfast(cnew.z);
            hnew.w = sigf(gv[3].w) * tanhfast(cnew.w);
            *(float4*)&g_c[hidx] = cnew;
            *(float4*)&g_h[hidx] = hnew;
            *(float4*)&out[((size_t)m * S_ + t) * H_ + nt * 64 + c4] = hnew;
        }
    }
}

// ---------------------------------------------------------------------------
// Launcher
// ---------------------------------------------------------------------------
extern "C" void kernel_launch(void* const* d_in, const int* in_sizes, int n_in,
                              void* d_out, int out_size) {
    const float* features = (const float*)d_in[0];
    const int*   captions = (const int*)  d_in[1];
    const float* W_embed  = (const float*)d_in[2];
    const float* b_embed  = (const float*)d_in[3];
    const float* w_ih     = (const float*)d_in[4];
    const float* w_hh     = (const float*)d_in[5];
    const float* b_ih     = (const float*)d_in[6];
    const float* b_hh     = (const float*)d_in[7];
    const float* h0       = (const float*)d_in[8];
    const float* c0       = (const float*)d_in[9];
    float* out = (float*)d_out;

    float *px, *pxg, *ph, *pc, *ppart;
    cudaGetSymbolAddress((void**)&px,    g_x);
    cudaGetSymbolAddress((void**)&pxg,   g_xg);
    cudaGetSymbolAddress((void**)&ph,    g_h);
    cudaGetSymbolAddress((void**)&pc,    g_c);
    cudaGetSymbolAddress((void**)&ppart, g_part);

    // 1) gather inputs (one-hot @ Linear == column gather)
    build_x_kernel<<<(M1 * E_ + 255) / 256, 256>>>(features, captions, W_embed, b_embed);

    // 2) input projection xg = x @ w_ih^T  (M=2112, N=4096, K=512)
    gemm_kernel<false><<<dim3(NTILES, M1 / BM, 1), NT>>>(
        px, w_ih, E_, E_, pxg, 0, nullptr, nullptr, nullptr, nullptr);

    // init recurrent state
    cudaMemcpyAsync(ph, h0, B_ * H_ * sizeof(float), cudaMemcpyDeviceToDevice, 0);
    cudaMemcpyAsync(pc, c0, B_ * H_ * sizeof(float), cudaMemcpyDeviceToDevice, 0);

    // 3) recurrence: one fused kernel per step (split-K GEMM + counter epilogue)
    for (int t = 0; t < S_; t++) {
        gemm_kernel<true><<<dim3(NTILES, 1, KSPLIT), NT>>>(
            ph, w_hh, H_, H_ / KSPLIT, ppart, t, pxg, b_ih, b_hh, out);
    }
}

// round 3
// speedup vs baseline: 1.2333x; 1.2333x over previous
#include <cuda_runtime.h>
#include <math.h>

// Problem constants
#define B_  64
#define T_  32
#define S_  33
#define V_  32000
#define E_  512
#define H_  1024
#define G4  4096
#define M1  (S_*B_)       // 2112

// GEMM config: CTA tile 64x256, 512 threads (16 warps), thread tile 8m x 4n
#define KSPLIT 8
#define BM 64
#define BN 256
#define BK 16
#define NT 512
#define NTILES (G4/BN)    // 16

// padded smem strides
#define ASTR 66
#define BSTR 260

// Scratch
__device__ float g_x   [M1 * E_];
__device__ float g_xg  [M1 * G4];
__device__ float g_h   [B_ * H_];
__device__ float g_c   [B_ * H_];
__device__ float g_part[KSPLIT * B_ * G4];
__device__ unsigned g_cnt[NTILES];

typedef unsigned long long u64;

__device__ __forceinline__ void ffma2(u64& d, u64 a, u64 b) {
    asm("fma.rn.f32x2 %0, %1, %2, %0;" : "+l"(d) : "l"(a), "l"(b));
}
__device__ __forceinline__ u64 splat2(float x) {
    u64 r; asm("mov.b64 %0, {%1, %1};" : "=l"(r) : "f"(x)); return r;
}
__device__ __forceinline__ float sigf(float x) {
    return 1.0f / (1.0f + __expf(-x));
}
__device__ __forceinline__ float tanhfast(float x) {
    return 2.0f / (1.0f + __expf(-2.0f * x)) - 1.0f;
}

// ---------------------------------------------------------------------------
// 1) Gather inputs: row m = t*64+b ; t==0 -> features, else W_embed column
// ---------------------------------------------------------------------------
__global__ void build_x_kernel(const float* __restrict__ features,
                               const int*   __restrict__ captions,
                               const float* __restrict__ W_embed,
                               const float* __restrict__ b_embed) {
    int idx = blockIdx.x * blockDim.x + threadIdx.x;
    if (idx >= M1 * E_) return;
    int m = idx >> 9;
    int e = idx & 511;
    int t = m >> 6;
    int b = m & 63;
    float v;
    if (t == 0) {
        v = features[b * E_ + e];
    } else {
        int cap = captions[b * T_ + (t - 1)];
        v = W_embed[e * V_ + cap] + b_embed[e];
    }
    g_x[idx] = v;
}

// ---------------------------------------------------------------------------
// 2) NT GEMM 64x256, 512 threads, 8m x 4n thread tile (m-packed f32x2),
//    double-buffered smem. STEP=true adds split-K partials + counter-gated
//    fused LSTM epilogue (gate-interleaved n-tiles).
// ---------------------------------------------------------------------------
template<bool STEP>
__global__ __launch_bounds__(NT, 1)
void gemm_kernel(const float* __restrict__ A,     // [M, K]
                 const float* __restrict__ Bw,    // [4096, K]
                 int K, int kLen,
                 float* C,                        // xg or partials
                 int t,
                 const float* __restrict__ xg,
                 const float* __restrict__ b_ih,
                 const float* __restrict__ b_hh,
                 float* __restrict__ out) {
    __shared__ float As[2][BK][ASTR];
    __shared__ float Bs[2][BK][BSTR];

    const int tid = threadIdx.x;
    const int nt  = blockIdx.x;
    const int m0  = blockIdx.y * BM;
    const int z   = blockIdx.z;
    const int kStart = z * kLen;

    // ---- global-load mapping ----
    // A: 64 rows x 4 k-quads = 256 float4 -> threads 0..255
    const int ar = (tid & 255) >> 2;
    const int aq = tid & 3;
    // B: 256 rows x 4 k-quads = 1024 float4 -> 2 per thread
    const int br = tid >> 2;            // 0..127
    const int bq = tid & 3;

    const float* Ap = A + (size_t)(m0 + ar) * K + kStart + aq * 4;
    const float* Bp[2];
#pragma unroll
    for (int i = 0; i < 2; i++) {
        int n = br + 128 * i;
        int grow;
        if (STEP) grow = (n >> 6) * H_ + nt * 64 + (n & 63);  // gate-interleaved
        else      grow = nt * BN + n;
        Bp[i] = Bw + (size_t)grow * K + kStart + bq * 4;
    }

    // ---- compute mapping: 8m x 4n ----
    const int mg = tid >> 6;   // 0..7 (warp-uniform)
    const int ng = tid & 63;   // 0..63

    u64 acc[4][4];
#pragma unroll
    for (int i = 0; i < 4; i++)
#pragma unroll
        for (int j = 0; j < 4; j++) acc[i][j] = 0ull;

    const int nk = kLen / BK;

    float4 pa, pb0, pb1;
    if (tid < 256) pa = *(const float4*)Ap;
    pb0 = *(const float4*)Bp[0];
    pb1 = *(const float4*)Bp[1];

    for (int kt = 0; kt < nk; kt++) {
        const int cur = kt & 1;
        if (tid < 256) {
            As[cur][aq * 4 + 0][ar] = pa.x;
            As[cur][aq * 4 + 1][ar] = pa.y;
            As[cur][aq * 4 + 2][ar] = pa.z;
            As[cur][aq * 4 + 3][ar] = pa.w;
        }
        Bs[cur][bq * 4 + 0][br]       = pb0.x;
        Bs[cur][bq * 4 + 1][br]       = pb0.y;
        Bs[cur][bq * 4 + 2][br]       = pb0.z;
        Bs[cur][bq * 4 + 3][br]       = pb0.w;
        Bs[cur][bq * 4 + 0][br + 128] = pb1.x;
        Bs[cur][bq * 4 + 1][br + 128] = pb1.y;
        Bs[cur][bq * 4 + 2][br + 128] = pb1.z;
        Bs[cur][bq * 4 + 3][br + 128] = pb1.w;
        __syncthreads();

        if (kt + 1 < nk) {
            int off = (kt + 1) * BK;
            if (tid < 256) pa = *(const float4*)(Ap + off);
            pb0 = *(const float4*)(Bp[0] + off);
            pb1 = *(const float4*)(Bp[1] + off);
        }

#pragma unroll
        for (int kk = 0; kk < BK; kk++) {
            u64 a0 = *(const u64*)&As[cur][kk][mg * 8 + 0];
            u64 a1 = *(const u64*)&As[cur][kk][mg * 8 + 2];
            u64 a2 = *(const u64*)&As[cur][kk][mg * 8 + 4];
            u64 a3 = *(const u64*)&As[cur][kk][mg * 8 + 6];
            float4 b4 = *(const float4*)&Bs[cur][kk][ng * 4];
            u64 sb0 = splat2(b4.x);
            u64 sb1 = splat2(b4.y);
            u64 sb2 = splat2(b4.z);
            u64 sb3 = splat2(b4.w);

            ffma2(acc[0][0], a0, sb0); ffma2(acc[0][1], a0, sb1);
            ffma2(acc[0][2], a0, sb2); ffma2(acc[0][3], a0, sb3);
            ffma2(acc[1][0], a1, sb0); ffma2(acc[1][1], a1, sb1);
            ffma2(acc[1][2], a1, sb2); ffma2(acc[1][3], a1, sb3);
            ffma2(acc[2][0], a2, sb0); ffma2(acc[2][1], a2, sb1);
            ffma2(acc[2][2], a2, sb2); ffma2(acc[2][3], a2, sb3);
            ffma2(acc[3][0], a3, sb0); ffma2(acc[3][1], a3, sb1);
            ffma2(acc[3][2], a3, sb2); ffma2(acc[3][3], a3, sb3);
        }
    }

    // store C (xg for input proj; k-split partial for step)
    {
        float* base;
        if (STEP) base = C + (size_t)z * (B_ * G4);
        else      base = C;
#pragma unroll
        for (int i = 0; i < 4; i++) {
            int m = m0 + mg * 8 + 2 * i;
            float* r0 = base + (size_t)m * G4 + nt * BN + ng * 4;
            float* r1 = r0 + G4;
#pragma unroll
            for (int j = 0; j < 4; j++) {
                float2 v = *(float2*)&acc[i][j];
                r0[j] = v.x;
                r1[j] = v.y;
            }
        }
    }

    if (STEP) {
        __threadfence();
        __shared__ unsigned s_last;
        __syncthreads();
        if (tid == 0) {
            unsigned old = atomicAdd(&g_cnt[nt], 1u);
            s_last = (old == KSPLIT - 1) ? 1u : 0u;
        }
        __syncthreads();
        if (!s_last) return;
        if (tid == 0) g_cnt[nt] = 0;
        __threadfence();

        // fused LSTM update: this n-tile's 64 cell columns x 64 batch rows
#pragma unroll
        for (int r = 0; r < 2; r++) {
            int id = r * NT + tid;       // 0..1023
            int m  = id >> 4;
            int c4 = (id & 15) * 4;
            float4 gv[4];
#pragma unroll
            for (int g = 0; g < 4; g++) {
                int ncol = g * H_ + nt * 64 + c4;
                float4 s  = *(const float4*)&xg[(size_t)(t * B_ + m) * G4 + ncol];
                float4 bi = *(const float4*)&b_ih[ncol];
                float4 bh = *(const float4*)&b_hh[ncol];
                s.x += bi.x + bh.x; s.y += bi.y + bh.y;
                s.z += bi.z + bh.z; s.w += bi.w + bh.w;
#pragma unroll
                for (int zz = 0; zz < KSPLIT; zz++) {
                    const float4 p = *(const float4*)
                        &g_part[(size_t)zz * (B_ * G4) + (size_t)m * G4 + nt * BN + g * 64 + c4];
                    s.x += p.x; s.y += p.y; s.z += p.z; s.w += p.w;
                }
                gv[g] = s;
            }
            int hidx = m * H_ + nt * 64 + c4;
            float4 cold = *(const float4*)&g_c[hidx];
            float4 cnew, hnew;
            cnew.x = sigf(gv[1].x) * cold.x + sigf(gv[0].x) * tanhfast(gv[2].x);
            cnew.y = sigf(gv[1].y) * cold.y + sigf(gv[0].y) * tanhfast(gv[2].y);
            cnew.z = sigf(gv[1].z) * cold.z + sigf(gv[0].z) * tanhfast(gv[2].z);
            cnew.w = sigf(gv[1].w) * cold.w + sigf(gv[0].w) * tanhfast(gv[2].w);
            hnew.x = sigf(gv[3].x) * tanhfast(cnew.x);
            hnew.y = sigf(gv[3].y) * tanhfast(cnew.y);
            hnew.z = sigf(gv[3].z) * tanhfast(cnew.z);
            hnew.w = sigf(gv[3].w) * tanhfast(cnew.w);
            *(float4*)&g_c[hidx] = cnew;
            *(float4*)&g_h[hidx] = hnew;
            *(float4*)&out[((size_t)m * S_ + t) * H_ + nt * 64 + c4] = hnew;
        }
    }
}

// ---------------------------------------------------------------------------
// Launcher
// ---------------------------------------------------------------------------
extern "C" void kernel_launch(void* const* d_in, const int* in_sizes, int n_in,
                              void* d_out, int out_size) {
    const float* features = (const float*)d_in[0];
    const int*   captions = (const int*)  d_in[1];
    const float* W_embed  = (const float*)d_in[2];
    const float* b_embed  = (const float*)d_in[3];
    const float* w_ih     = (const float*)d_in[4];
    const float* w_hh     = (const float*)d_in[5];
    const float* b_ih     = (const float*)d_in[6];
    const float* b_hh     = (const float*)d_in[7];
    const float* h0       = (const float*)d_in[8];
    const float* c0       = (const float*)d_in[9];
    float* out = (float*)d_out;

    float *px, *pxg, *ph, *pc, *ppart;
    cudaGetSymbolAddress((void**)&px,    g_x);
    cudaGetSymbolAddress((void**)&pxg,   g_xg);
    cudaGetSymbolAddress((void**)&ph,    g_h);
    cudaGetSymbolAddress((void**)&pc,    g_c);
    cudaGetSymbolAddress((void**)&ppart, g_part);

    // 1) gather inputs
    build_x_kernel<<<(M1 * E_ + 255) / 256, 256>>>(features, captions, W_embed, b_embed);

    // 2) input projection xg = x @ w_ih^T  (M=2112, N=4096, K=512)
    gemm_kernel<false><<<dim3(NTILES, M1 / BM, 1), NT>>>(
        px, w_ih, E_, E_, pxg, 0, nullptr, nullptr, nullptr, nullptr);

    // init recurrent state
    cudaMemcpyAsync(ph, h0, B_ * H_ * sizeof(float), cudaMemcpyDeviceToDevice, 0);
    cudaMemcpyAsync(pc, c0, B_ * H_ * sizeof(float), cudaMemcpyDeviceToDevice, 0);

    // 3) recurrence: fused split-K GEMM + LSTM epilogue per step
    for (int t = 0; t < S_; t++) {
        gemm_kernel<true><<<dim3(NTILES, 1, KSPLIT), NT>>>(
            ph, w_hh, H_, H_ / KSPLIT, ppart, t, pxg, b_ih, b_hh, out);
    }
}